// round 1
// baseline (speedup 1.0000x reference)
#include <cuda_runtime.h>
#include <math.h>

#define Dm   1024
#define Hh   16
#define DKk  64
#define Bb   4
#define Ll   2048
#define MTOT (Bb * Ll)   // 8192

// Scratch (no allocations allowed) — 4 x 32 MB
__device__ float g_Q[MTOT * Dm];
__device__ float g_K[MTOT * Dm];
__device__ float g_V[MTOT * Dm];
__device__ float g_CTX[MTOT * Dm];

// ---------------------------------------------------------------------------
// SGEMM: C[M,N] = A[M,K] @ W[N,K]^T + bias[N]
// BM=BN=64, BK=16, 256 threads, 4x4 microtile, smem tiles stored k-major.
// ---------------------------------------------------------------------------
__global__ __launch_bounds__(256)
void sgemm_bt_bias(const float* __restrict__ A, const float* __restrict__ W,
                   const float* __restrict__ bias, float* __restrict__ C,
                   int M, int N, int K)
{
    __shared__ float As[16][68];
    __shared__ float Bs[16][68];

    const int tid = threadIdx.x;
    const int tx  = tid & 15;
    const int ty  = tid >> 4;
    const int m0  = blockIdx.y * 64;
    const int n0  = blockIdx.x * 64;

    const int lr = tid >> 2;         // 0..63 (row in tile)
    const int lk = (tid & 3) << 2;   // 0,4,8,12 (k offset)

    const float* Aptr = A + (size_t)(m0 + lr) * K + lk;
    const float* Wptr = W + (size_t)(n0 + lr) * K + lk;

    float acc[4][4] = {};

    for (int k0 = 0; k0 < K; k0 += 16) {
        float4 a4 = *(const float4*)(Aptr + k0);
        float4 b4 = *(const float4*)(Wptr + k0);
        As[lk + 0][lr] = a4.x; As[lk + 1][lr] = a4.y;
        As[lk + 2][lr] = a4.z; As[lk + 3][lr] = a4.w;
        Bs[lk + 0][lr] = b4.x; Bs[lk + 1][lr] = b4.y;
        Bs[lk + 2][lr] = b4.z; Bs[lk + 3][lr] = b4.w;
        __syncthreads();

        #pragma unroll
        for (int ks = 0; ks < 16; ks++) {
            float4 av = *(const float4*)&As[ks][ty * 4];
            float4 bv = *(const float4*)&Bs[ks][tx * 4];
            float a[4] = {av.x, av.y, av.z, av.w};
            float b[4] = {bv.x, bv.y, bv.z, bv.w};
            #pragma unroll
            for (int i = 0; i < 4; i++)
                #pragma unroll
                for (int j = 0; j < 4; j++)
                    acc[i][j] += a[i] * b[j];
        }
        __syncthreads();
    }

    #pragma unroll
    for (int i = 0; i < 4; i++) {
        const int m = m0 + ty * 4 + i;
        float* crow = C + (size_t)m * N + n0 + tx * 4;
        const float* brow = bias + n0 + tx * 4;
        float4 o;
        o.x = acc[i][0] + brow[0];
        o.y = acc[i][1] + brow[1];
        o.z = acc[i][2] + brow[2];
        o.w = acc[i][3] + brow[3];
        *(float4*)crow = o;
    }
}

// ---------------------------------------------------------------------------
// Flash attention (causal), fp32. One block = (b, h, 64-row q tile).
// 256 threads, 4x4 microtiles for both S = Q K^T and O += P V.
// smem: Qts[d][r], Kts[d][c], Vs[j][d], Ps[r][j]; all stride 68.
// ---------------------------------------------------------------------------
#define ST 68
#define ATT_SMEM_FLOATS (4 * 64 * ST)

__device__ __forceinline__ float redmax16(float v) {
    v = fmaxf(v, __shfl_xor_sync(0xffffffffu, v, 1));
    v = fmaxf(v, __shfl_xor_sync(0xffffffffu, v, 2));
    v = fmaxf(v, __shfl_xor_sync(0xffffffffu, v, 4));
    v = fmaxf(v, __shfl_xor_sync(0xffffffffu, v, 8));
    return v;
}
__device__ __forceinline__ float redsum16(float v) {
    v += __shfl_xor_sync(0xffffffffu, v, 1);
    v += __shfl_xor_sync(0xffffffffu, v, 2);
    v += __shfl_xor_sync(0xffffffffu, v, 4);
    v += __shfl_xor_sync(0xffffffffu, v, 8);
    return v;
}

__global__ __launch_bounds__(256)
void attn_kernel(const float* __restrict__ Q, const float* __restrict__ K,
                 const float* __restrict__ V, float* __restrict__ O)
{
    extern __shared__ float sm[];
    float* Qts = sm;                  // [64][ST]  Qts[d*ST + r]
    float* Kts = sm + 64 * ST;        // [64][ST]  Kts[d*ST + c]
    float* Vs  = sm + 2 * 64 * ST;    // [64][ST]  Vs[j*ST + d]
    float* Ps  = sm + 3 * 64 * ST;    // [64][ST]  Ps[r*ST + j]

    const int tid = threadIdx.x;
    const int tx  = tid & 15;
    const int ty  = tid >> 4;
    const int qt  = blockIdx.x;       // 0..31
    const int h   = blockIdx.y;
    const int b   = blockIdx.z;
    const int q0  = qt * 64;

    const float* Qb = Q + (size_t)b * Ll * Dm + h * DKk;
    const float* Kb = K + (size_t)b * Ll * Dm + h * DKk;
    const float* Vb = V + (size_t)b * Ll * Dm + h * DKk;

    const int lrow = tid >> 2;        // 0..63
    const int lseg = tid & 3;         // float4 segment base

    // Load Q tile (transposed into Qts[d][r])
    #pragma unroll
    for (int p = 0; p < 4; p++) {
        const int seg = lseg + p * 4;       // 0..15
        float4 v4 = *(const float4*)(Qb + (size_t)(q0 + lrow) * Dm + seg * 4);
        Qts[(seg * 4 + 0) * ST + lrow] = v4.x;
        Qts[(seg * 4 + 1) * ST + lrow] = v4.y;
        Qts[(seg * 4 + 2) * ST + lrow] = v4.z;
        Qts[(seg * 4 + 3) * ST + lrow] = v4.w;
    }

    float m_i[4], l_i[4], o[4][4];
    #pragma unroll
    for (int i = 0; i < 4; i++) {
        m_i[i] = -1e30f; l_i[i] = 0.f;
        #pragma unroll
        for (int j = 0; j < 4; j++) o[i][j] = 0.f;
    }

    for (int kt = 0; kt <= qt; kt++) {
        const int k0 = kt * 64;

        // Load K tile (transposed) and V tile (natural)
        #pragma unroll
        for (int p = 0; p < 4; p++) {
            const int seg = lseg + p * 4;
            float4 kv = *(const float4*)(Kb + (size_t)(k0 + lrow) * Dm + seg * 4);
            Kts[(seg * 4 + 0) * ST + lrow] = kv.x;
            Kts[(seg * 4 + 1) * ST + lrow] = kv.y;
            Kts[(seg * 4 + 2) * ST + lrow] = kv.z;
            Kts[(seg * 4 + 3) * ST + lrow] = kv.w;
            float4 vv = *(const float4*)(Vb + (size_t)(k0 + lrow) * Dm + seg * 4);
            *(float4*)&Vs[lrow * ST + seg * 4] = vv;
        }
        __syncthreads();

        // S = (Q K^T) * scale
        float s[4][4] = {};
        #pragma unroll 8
        for (int d = 0; d < 64; d++) {
            float4 qv = *(const float4*)&Qts[d * ST + ty * 4];
            float4 kv = *(const float4*)&Kts[d * ST + tx * 4];
            float qa[4] = {qv.x, qv.y, qv.z, qv.w};
            float ka[4] = {kv.x, kv.y, kv.z, kv.w};
            #pragma unroll
            for (int i = 0; i < 4; i++)
                #pragma unroll
                for (int j = 0; j < 4; j++)
                    s[i][j] += qa[i] * ka[j];
        }
        #pragma unroll
        for (int i = 0; i < 4; i++)
            #pragma unroll
            for (int j = 0; j < 4; j++)
                s[i][j] *= 0.125f;   // 1/sqrt(64)

        if (kt == qt) {   // diagonal tile: causal mask
            #pragma unroll
            for (int i = 0; i < 4; i++) {
                const int qi = q0 + ty * 4 + i;
                #pragma unroll
                for (int j = 0; j < 4; j++)
                    if (k0 + tx * 4 + j > qi) s[i][j] = -1e30f;
            }
        }

        // Online softmax update
        #pragma unroll
        for (int i = 0; i < 4; i++) {
            float rm = fmaxf(fmaxf(s[i][0], s[i][1]), fmaxf(s[i][2], s[i][3]));
            rm = redmax16(rm);
            const float m_new = fmaxf(m_i[i], rm);
            const float alpha = __expf(m_i[i] - m_new);
            float4 p4;
            p4.x = __expf(s[i][0] - m_new);
            p4.y = __expf(s[i][1] - m_new);
            p4.z = __expf(s[i][2] - m_new);
            p4.w = __expf(s[i][3] - m_new);
            float rs = redsum16(p4.x + p4.y + p4.z + p4.w);
            l_i[i] = l_i[i] * alpha + rs;
            m_i[i] = m_new;
            #pragma unroll
            for (int j = 0; j < 4; j++) o[i][j] *= alpha;
            *(float4*)&Ps[(ty * 4 + i) * ST + tx * 4] = p4;
        }
        __syncthreads();

        // O += P V
        #pragma unroll 8
        for (int kk = 0; kk < 64; kk++) {
            float4 vv = *(const float4*)&Vs[kk * ST + tx * 4];
            float va[4] = {vv.x, vv.y, vv.z, vv.w};
            float pr[4];
            #pragma unroll
            for (int i = 0; i < 4; i++) pr[i] = Ps[(ty * 4 + i) * ST + kk];
            #pragma unroll
            for (int i = 0; i < 4; i++)
                #pragma unroll
                for (int j = 0; j < 4; j++)
                    o[i][j] += pr[i] * va[j];
        }
        __syncthreads();
    }

    // Normalize and write [B,L,D] context
    #pragma unroll
    for (int i = 0; i < 4; i++) {
        const float inv = 1.0f / l_i[i];
        float* orow = O + (size_t)(b * Ll + q0 + ty * 4 + i) * Dm + h * DKk + tx * 4;
        float4 ov;
        ov.x = o[i][0] * inv; ov.y = o[i][1] * inv;
        ov.z = o[i][2] * inv; ov.w = o[i][3] * inv;
        *(float4*)orow = ov;
    }
}

// ---------------------------------------------------------------------------
extern "C" void kernel_launch(void* const* d_in, const int* in_sizes, int n_in,
                              void* d_out, int out_size)
{
    const float* q    = (const float*)d_in[0];
    const float* k    = (const float*)d_in[1];
    const float* v    = (const float*)d_in[2];
    const float* wq_w = (const float*)d_in[3];
    const float* wq_b = (const float*)d_in[4];
    const float* wk_w = (const float*)d_in[5];
    const float* wk_b = (const float*)d_in[6];
    const float* wv_w = (const float*)d_in[7];
    const float* wv_b = (const float*)d_in[8];
    const float* wo_w = (const float*)d_in[9];
    const float* wo_b = (const float*)d_in[10];
    float* out = (float*)d_out;

    float *Qs, *Ks, *Vs, *Cs;
    cudaGetSymbolAddress((void**)&Qs, g_Q);
    cudaGetSymbolAddress((void**)&Ks, g_K);
    cudaGetSymbolAddress((void**)&Vs, g_V);
    cudaGetSymbolAddress((void**)&Cs, g_CTX);

    const int smem_attn = ATT_SMEM_FLOATS * (int)sizeof(float);  // 69632
    cudaFuncSetAttribute(attn_kernel, cudaFuncAttributeMaxDynamicSharedMemorySize,
                         smem_attn);

    dim3 gg(Dm / 64, MTOT / 64);   // (16, 128)
    dim3 bk(256);

    sgemm_bt_bias<<<gg, bk>>>(q, wq_w, wq_b, Qs, MTOT, Dm, Dm);
    sgemm_bt_bias<<<gg, bk>>>(k, wk_w, wk_b, Ks, MTOT, Dm, Dm);
    sgemm_bt_bias<<<gg, bk>>>(v, wv_w, wv_b, Vs, MTOT, Dm, Dm);

    dim3 ga(Ll / 64, Hh, Bb);      // (32, 16, 4)
    attn_kernel<<<ga, bk, smem_attn>>>(Qs, Ks, Vs, Cs);

    sgemm_bt_bias<<<gg, bk>>>(Cs, wo_w, wo_b, out, MTOT, Dm, Dm);
}

// round 3
// speedup vs baseline: 1.8699x; 1.8699x over previous
#include <cuda_runtime.h>
#include <math.h>
#include <stdint.h>

#define Dm   1024
#define Hh   16
#define DKk  64
#define Bb   4
#define Ll   2048
#define MTOT (Bb * Ll)   // 8192

// Scratch (no allocations allowed) — 4 x 32 MB
__device__ float g_Q[MTOT * Dm];
__device__ float g_K[MTOT * Dm];
__device__ float g_V[MTOT * Dm];
__device__ float g_CTX[MTOT * Dm];

__device__ __forceinline__ uint32_t smem_u32(const void* p) {
    uint32_t a;
    asm("{ .reg .u64 t; cvta.to.shared.u64 t, %1; cvt.u32.u64 %0, t; }"
        : "=r"(a) : "l"(p));
    return a;
}

__device__ __forceinline__ uint32_t f2tf32(float x) {
    uint32_t u;
    asm("cvt.rna.tf32.f32 %0, %1;" : "=r"(u) : "f"(x));
    return u;
}

__device__ __forceinline__ void mma_tf32(float d[4], const uint32_t a[4],
                                         const uint32_t b[2]) {
    asm volatile(
        "mma.sync.aligned.m16n8k8.row.col.f32.tf32.tf32.f32 "
        "{%0,%1,%2,%3}, {%4,%5,%6,%7}, {%8,%9}, {%0,%1,%2,%3};"
        : "+f"(d[0]), "+f"(d[1]), "+f"(d[2]), "+f"(d[3])
        : "r"(a[0]), "r"(a[1]), "r"(a[2]), "r"(a[3]), "r"(b[0]), "r"(b[1]));
}

// ---------------------------------------------------------------------------
// mma.sync tf32 GEMM: C[M,N] = A[M,K] @ W[N,K]^T + bias.  M=8192, N=K=1024.
// CTA 128x128 (128 thr, 4 warps of 64x64), K chunks of 32, cp.async dbl-buf.
// smem rows padded to 36 floats -> conflict-free fragment LDS.
// ---------------------------------------------------------------------------
#define GK      1024
#define GN      1024
#define KCH     32
#define NCHUNK  (GK / KCH)            // 32
#define APAD    36                    // floats per smem row
#define TILE_F  (128 * APAD)          // 4608 floats per tile
#define GEMM_DYN_SMEM (4 * TILE_F * 4)  // 73728 B

__global__ __launch_bounds__(128, 2)
void gemm_mma_tf32(const float* __restrict__ A, const float* __restrict__ W,
                   const float* __restrict__ bias, float* __restrict__ C)
{
    extern __shared__ float sm[];
    float* sA = sm;                 // [2][TILE_F]
    float* sB = sm + 2 * TILE_F;    // [2][TILE_F]

    const int tid  = threadIdx.x;
    const int warp = tid >> 5;
    const int lane = tid & 31;
    const int wm   = warp & 1;      // warp row (0..1)
    const int wn   = warp >> 1;     // warp col (0..1)
    const int m0   = blockIdx.y * 128;
    const int n0   = blockIdx.x * 128;

    const int fr = tid >> 3;        // fill row 0..15 base
    const int fg = tid & 7;         // fill float4 group 0..7

    float d[4][8][4];
    #pragma unroll
    for (int mi = 0; mi < 4; mi++)
        #pragma unroll
        for (int ni = 0; ni < 8; ni++)
            #pragma unroll
            for (int r = 0; r < 4; r++) d[mi][ni][r] = 0.f;

    // cp.async fill of chunk c into stage s
    auto fill = [&](int c, int s) {
        const int k0 = c * KCH;
        const float* Ag = A + (size_t)m0 * GK + k0;
        const float* Wg = W + (size_t)n0 * GK + k0;
        float* dA = sA + s * TILE_F;
        float* dB = sB + s * TILE_F;
        #pragma unroll
        for (int i = 0; i < 8; i++) {
            const int r = fr + i * 16;                 // 0..127
            const uint32_t so = (uint32_t)(r * APAD + fg * 4);
            uint32_t da = smem_u32(dA + so);
            const float* ga = Ag + (size_t)r * GK + fg * 4;
            asm volatile("cp.async.cg.shared.global [%0], [%1], 16;"
                         :: "r"(da), "l"(ga));
            uint32_t db = smem_u32(dB + so);
            const float* gb = Wg + (size_t)r * GK + fg * 4;
            asm volatile("cp.async.cg.shared.global [%0], [%1], 16;"
                         :: "r"(db), "l"(gb));
        }
        asm volatile("cp.async.commit_group;");
    };

    fill(0, 0);
    fill(1, 1);

    for (int c = 0; c < NCHUNK; c++) {
        const int s = c & 1;
        asm volatile("cp.async.wait_group 1;" ::: "memory");
        __syncthreads();

        const float* tA = sA + s * TILE_F + (wm * 64 + (lane >> 2)) * APAD + (lane & 3);
        const float* tB = sB + s * TILE_F + (wn * 64 + (lane >> 2)) * APAD + (lane & 3);

        #pragma unroll
        for (int j = 0; j < 4; j++) {        // 4 k-steps of 8
            uint32_t af[4][4], bf[8][2];
            #pragma unroll
            for (int mi = 0; mi < 4; mi++) {
                const float* p = tA + mi * 16 * APAD + j * 8;
                af[mi][0] = f2tf32(p[0]);
                af[mi][1] = f2tf32(p[8 * APAD]);
                af[mi][2] = f2tf32(p[4]);
                af[mi][3] = f2tf32(p[8 * APAD + 4]);
            }
            #pragma unroll
            for (int ni = 0; ni < 8; ni++) {
                const float* p = tB + ni * 8 * APAD + j * 8;
                bf[ni][0] = f2tf32(p[0]);
                bf[ni][1] = f2tf32(p[4]);
            }
            #pragma unroll
            for (int mi = 0; mi < 4; mi++)
                #pragma unroll
                for (int ni = 0; ni < 8; ni++)
                    mma_tf32(d[mi][ni], af[mi], bf[ni]);
        }
        __syncthreads();
        if (c + 2 < NCHUNK) fill(c + 2, s);
    }

    // Epilogue: bias add + store
    const int row0 = m0 + wm * 64 + (lane >> 2);
    const int col0 = n0 + wn * 64 + 2 * (lane & 3);
    #pragma unroll
    for (int ni = 0; ni < 8; ni++) {
        const int cc = col0 + ni * 8;
        const float b0 = bias[cc], b1 = bias[cc + 1];
        #pragma unroll
        for (int mi = 0; mi < 4; mi++) {
            const int r = row0 + mi * 16;
            float2 v0 = {d[mi][ni][0] + b0, d[mi][ni][1] + b1};
            float2 v1 = {d[mi][ni][2] + b0, d[mi][ni][3] + b1};
            *(float2*)(C + (size_t)r * GN + cc) = v0;
            *(float2*)(C + (size_t)(r + 8) * GN + cc) = v1;
        }
    }
}

// ---------------------------------------------------------------------------
// Flash attention (causal), fp32 — unchanged (passed R1).
// ---------------------------------------------------------------------------
#define ST 68
#define ATT_SMEM_FLOATS (4 * 64 * ST)

__device__ __forceinline__ float redmax16(float v) {
    v = fmaxf(v, __shfl_xor_sync(0xffffffffu, v, 1));
    v = fmaxf(v, __shfl_xor_sync(0xffffffffu, v, 2));
    v = fmaxf(v, __shfl_xor_sync(0xffffffffu, v, 4));
    v = fmaxf(v, __shfl_xor_sync(0xffffffffu, v, 8));
    return v;
}
__device__ __forceinline__ float redsum16(float v) {
    v += __shfl_xor_sync(0xffffffffu, v, 1);
    v += __shfl_xor_sync(0xffffffffu, v, 2);
    v += __shfl_xor_sync(0xffffffffu, v, 4);
    v += __shfl_xor_sync(0xffffffffu, v, 8);
    return v;
}

__global__ __launch_bounds__(256)
void attn_kernel(const float* __restrict__ Q, const float* __restrict__ K,
                 const float* __restrict__ V, float* __restrict__ O)
{
    extern __shared__ float smf[];
    float* Qts = smf;                  // [64][ST]  Qts[d*ST + r]
    float* Kts = smf + 64 * ST;        // [64][ST]  Kts[d*ST + c]
    float* Vs  = smf + 2 * 64 * ST;    // [64][ST]  Vs[j*ST + d]
    float* Ps  = smf + 3 * 64 * ST;    // [64][ST]  Ps[r*ST + j]

    const int tid = threadIdx.x;
    const int tx  = tid & 15;
    const int ty  = tid >> 4;
    const int qt  = blockIdx.x;
    const int h   = blockIdx.y;
    const int b   = blockIdx.z;
    const int q0  = qt * 64;

    const float* Qb = Q + (size_t)b * Ll * Dm + h * DKk;
    const float* Kb = K + (size_t)b * Ll * Dm + h * DKk;
    const float* Vb = V + (size_t)b * Ll * Dm + h * DKk;

    const int lrow = tid >> 2;
    const int lseg = tid & 3;

    #pragma unroll
    for (int p = 0; p < 4; p++) {
        const int seg = lseg + p * 4;
        float4 v4 = *(const float4*)(Qb + (size_t)(q0 + lrow) * Dm + seg * 4);
        Qts[(seg * 4 + 0) * ST + lrow] = v4.x;
        Qts[(seg * 4 + 1) * ST + lrow] = v4.y;
        Qts[(seg * 4 + 2) * ST + lrow] = v4.z;
        Qts[(seg * 4 + 3) * ST + lrow] = v4.w;
    }

    float m_i[4], l_i[4], o[4][4];
    #pragma unroll
    for (int i = 0; i < 4; i++) {
        m_i[i] = -1e30f; l_i[i] = 0.f;
        #pragma unroll
        for (int j = 0; j < 4; j++) o[i][j] = 0.f;
    }

    for (int kt = 0; kt <= qt; kt++) {
        const int k0 = kt * 64;

        #pragma unroll
        for (int p = 0; p < 4; p++) {
            const int seg = lseg + p * 4;
            float4 kv = *(const float4*)(Kb + (size_t)(k0 + lrow) * Dm + seg * 4);
            Kts[(seg * 4 + 0) * ST + lrow] = kv.x;
            Kts[(seg * 4 + 1) * ST + lrow] = kv.y;
            Kts[(seg * 4 + 2) * ST + lrow] = kv.z;
            Kts[(seg * 4 + 3) * ST + lrow] = kv.w;
            float4 vv = *(const float4*)(Vb + (size_t)(k0 + lrow) * Dm + seg * 4);
            *(float4*)&Vs[lrow * ST + seg * 4] = vv;
        }
        __syncthreads();

        float s[4][4] = {};
        #pragma unroll 8
        for (int dd = 0; dd < 64; dd++) {
            float4 qv = *(const float4*)&Qts[dd * ST + ty * 4];
            float4 kv = *(const float4*)&Kts[dd * ST + tx * 4];
            float qa[4] = {qv.x, qv.y, qv.z, qv.w};
            float ka[4] = {kv.x, kv.y, kv.z, kv.w};
            #pragma unroll
            for (int i = 0; i < 4; i++)
                #pragma unroll
                for (int j = 0; j < 4; j++)
                    s[i][j] += qa[i] * ka[j];
        }
        #pragma unroll
        for (int i = 0; i < 4; i++)
            #pragma unroll
            for (int j = 0; j < 4; j++)
                s[i][j] *= 0.125f;

        if (kt == qt) {
            #pragma unroll
            for (int i = 0; i < 4; i++) {
                const int qi = q0 + ty * 4 + i;
                #pragma unroll
                for (int j = 0; j < 4; j++)
                    if (k0 + tx * 4 + j > qi) s[i][j] = -1e30f;
            }
        }

        #pragma unroll
        for (int i = 0; i < 4; i++) {
            float rm = fmaxf(fmaxf(s[i][0], s[i][1]), fmaxf(s[i][2], s[i][3]));
            rm = redmax16(rm);
            const float m_new = fmaxf(m_i[i], rm);
            const float alpha = __expf(m_i[i] - m_new);
            float4 p4;
            p4.x = __expf(s[i][0] - m_new);
            p4.y = __expf(s[i][1] - m_new);
            p4.z = __expf(s[i][2] - m_new);
            p4.w = __expf(s[i][3] - m_new);
            float rs = redsum16(p4.x + p4.y + p4.z + p4.w);
            l_i[i] = l_i[i] * alpha + rs;
            m_i[i] = m_new;
            #pragma unroll
            for (int j = 0; j < 4; j++) o[i][j] *= alpha;
            *(float4*)&Ps[(ty * 4 + i) * ST + tx * 4] = p4;
        }
        __syncthreads();

        #pragma unroll 8
        for (int kk = 0; kk < 64; kk++) {
            float4 vv = *(const float4*)&Vs[kk * ST + tx * 4];
            float va[4] = {vv.x, vv.y, vv.z, vv.w};
            float pr[4];
            #pragma unroll
            for (int i = 0; i < 4; i++) pr[i] = Ps[(ty * 4 + i) * ST + kk];
            #pragma unroll
            for (int i = 0; i < 4; i++)
                #pragma unroll
                for (int j = 0; j < 4; j++)
                    o[i][j] += pr[i] * va[j];
        }
        __syncthreads();
    }

    #pragma unroll
    for (int i = 0; i < 4; i++) {
        const float inv = 1.0f / l_i[i];
        float* orow = O + (size_t)(b * Ll + q0 + ty * 4 + i) * Dm + h * DKk + tx * 4;
        float4 ov;
        ov.x = o[i][0] * inv; ov.y = o[i][1] * inv;
        ov.z = o[i][2] * inv; ov.w = o[i][3] * inv;
        *(float4*)orow = ov;
    }
}

// ---------------------------------------------------------------------------
extern "C" void kernel_launch(void* const* d_in, const int* in_sizes, int n_in,
                              void* d_out, int out_size)
{
    const float* q    = (const float*)d_in[0];
    const float* k    = (const float*)d_in[1];
    const float* v    = (const float*)d_in[2];
    const float* wq_w = (const float*)d_in[3];
    const float* wq_b = (const float*)d_in[4];
    const float* wk_w = (const float*)d_in[5];
    const float* wk_b = (const float*)d_in[6];
    const float* wv_w = (const float*)d_in[7];
    const float* wv_b = (const float*)d_in[8];
    const float* wo_w = (const float*)d_in[9];
    const float* wo_b = (const float*)d_in[10];
    float* out = (float*)d_out;

    float *Qs, *Ks, *Vs, *Cs;
    cudaGetSymbolAddress((void**)&Qs, g_Q);
    cudaGetSymbolAddress((void**)&Ks, g_K);
    cudaGetSymbolAddress((void**)&Vs, g_V);
    cudaGetSymbolAddress((void**)&Cs, g_CTX);

    const int smem_attn = ATT_SMEM_FLOATS * (int)sizeof(float);  // 69632
    cudaFuncSetAttribute(attn_kernel, cudaFuncAttributeMaxDynamicSharedMemorySize,
                         smem_attn);
    cudaFuncSetAttribute(gemm_mma_tf32, cudaFuncAttributeMaxDynamicSharedMemorySize,
                         GEMM_DYN_SMEM);

    dim3 gg(GN / 128, MTOT / 128);   // (8, 64)
    dim3 gbk(128);

    gemm_mma_tf32<<<gg, gbk, GEMM_DYN_SMEM>>>(q, wq_w, wq_b, Qs);
    gemm_mma_tf32<<<gg, gbk, GEMM_DYN_SMEM>>>(k, wk_w, wk_b, Ks);
    gemm_mma_tf32<<<gg, gbk, GEMM_DYN_SMEM>>>(v, wv_w, wv_b, Vs);

    dim3 ga(Ll / 64, Hh, Bb);        // (32, 16, 4)
    attn_kernel<<<ga, 256, smem_attn>>>(Qs, Ks, Vs, Cs);

    gemm_mma_tf32<<<gg, gbk, GEMM_DYN_SMEM>>>(Cs, wo_w, wo_b, out);
}

// round 4
// speedup vs baseline: 3.4998x; 1.8716x over previous
#include <cuda_runtime.h>
#include <math.h>
#include <stdint.h>

#define Dm   1024
#define Hh   16
#define DKk  64
#define Bb   4
#define Ll   2048
#define MTOT (Bb * Ll)   // 8192

// Scratch (no allocations allowed) — 4 x 32 MB
__device__ float g_Q[MTOT * Dm];
__device__ float g_K[MTOT * Dm];
__device__ float g_V[MTOT * Dm];
__device__ float g_CTX[MTOT * Dm];

__device__ __forceinline__ uint32_t smem_u32(const void* p) {
    uint32_t a;
    asm("{ .reg .u64 t; cvta.to.shared.u64 t, %1; cvt.u32.u64 %0, t; }"
        : "=r"(a) : "l"(p));
    return a;
}

__device__ __forceinline__ uint32_t f2tf32(float x) {
    uint32_t u;
    asm("cvt.rna.tf32.f32 %0, %1;" : "=r"(u) : "f"(x));
    return u;
}

__device__ __forceinline__ void mma_tf32(float d[4], const uint32_t a[4],
                                         const uint32_t b[2]) {
    asm volatile(
        "mma.sync.aligned.m16n8k8.row.col.f32.tf32.tf32.f32 "
        "{%0,%1,%2,%3}, {%4,%5,%6,%7}, {%8,%9}, {%0,%1,%2,%3};"
        : "+f"(d[0]), "+f"(d[1]), "+f"(d[2]), "+f"(d[3])
        : "r"(a[0]), "r"(a[1]), "r"(a[2]), "r"(a[3]), "r"(b[0]), "r"(b[1]));
}

#define CP16(smaddr, gptr) \
    asm volatile("cp.async.cg.shared.global [%0], [%1], 16;" \
                 :: "r"(smaddr), "l"(gptr))

// ---------------------------------------------------------------------------
// mma.sync tf32 GEMM: C[M,N] = A[M,K] @ W[N,K]^T + bias.  M=8192, N=K=1024.
// tf32_out != 0 -> round outputs to tf32 (consumed by attention MMAs).
// ---------------------------------------------------------------------------
#define GK      1024
#define GN      1024
#define KCH     32
#define NCHUNK  (GK / KCH)            // 32
#define APAD    36
#define TILE_F  (128 * APAD)
#define GEMM_DYN_SMEM (4 * TILE_F * 4)  // 73728 B

__global__ __launch_bounds__(128, 2)
void gemm_mma_tf32(const float* __restrict__ A, const float* __restrict__ W,
                   const float* __restrict__ bias, float* __restrict__ C,
                   int tf32_out)
{
    extern __shared__ float sm[];
    float* sA = sm;
    float* sB = sm + 2 * TILE_F;

    const int tid  = threadIdx.x;
    const int warp = tid >> 5;
    const int lane = tid & 31;
    const int wm   = warp & 1;
    const int wn   = warp >> 1;
    const int m0   = blockIdx.y * 128;
    const int n0   = blockIdx.x * 128;

    const int fr = tid >> 3;
    const int fg = tid & 7;

    float d[4][8][4];
    #pragma unroll
    for (int mi = 0; mi < 4; mi++)
        #pragma unroll
        for (int ni = 0; ni < 8; ni++)
            #pragma unroll
            for (int r = 0; r < 4; r++) d[mi][ni][r] = 0.f;

    auto fill = [&](int c, int s) {
        const int k0 = c * KCH;
        const float* Ag = A + (size_t)m0 * GK + k0;
        const float* Wg = W + (size_t)n0 * GK + k0;
        float* dA = sA + s * TILE_F;
        float* dB = sB + s * TILE_F;
        #pragma unroll
        for (int i = 0; i < 8; i++) {
            const int r = fr + i * 16;
            const uint32_t so = (uint32_t)(r * APAD + fg * 4);
            CP16(smem_u32(dA + so), Ag + (size_t)r * GK + fg * 4);
            CP16(smem_u32(dB + so), Wg + (size_t)r * GK + fg * 4);
        }
        asm volatile("cp.async.commit_group;");
    };

    fill(0, 0);
    fill(1, 1);

    for (int c = 0; c < NCHUNK; c++) {
        const int s = c & 1;
        asm volatile("cp.async.wait_group 1;" ::: "memory");
        __syncthreads();

        const float* tA = sA + s * TILE_F + (wm * 64 + (lane >> 2)) * APAD + (lane & 3);
        const float* tB = sB + s * TILE_F + (wn * 64 + (lane >> 2)) * APAD + (lane & 3);

        #pragma unroll
        for (int j = 0; j < 4; j++) {
            uint32_t af[4][4], bf[8][2];
            #pragma unroll
            for (int mi = 0; mi < 4; mi++) {
                const float* p = tA + mi * 16 * APAD + j * 8;
                af[mi][0] = f2tf32(p[0]);
                af[mi][1] = f2tf32(p[8 * APAD]);
                af[mi][2] = f2tf32(p[4]);
                af[mi][3] = f2tf32(p[8 * APAD + 4]);
            }
            #pragma unroll
            for (int ni = 0; ni < 8; ni++) {
                const float* p = tB + ni * 8 * APAD + j * 8;
                bf[ni][0] = f2tf32(p[0]);
                bf[ni][1] = f2tf32(p[4]);
            }
            #pragma unroll
            for (int mi = 0; mi < 4; mi++)
                #pragma unroll
                for (int ni = 0; ni < 8; ni++)
                    mma_tf32(d[mi][ni], af[mi], bf[ni]);
        }
        __syncthreads();
        if (c + 2 < NCHUNK) fill(c + 2, s);
    }

    const int row0 = m0 + wm * 64 + (lane >> 2);
    const int col0 = n0 + wn * 64 + 2 * (lane & 3);
    #pragma unroll
    for (int ni = 0; ni < 8; ni++) {
        const int cc = col0 + ni * 8;
        const float b0 = bias[cc], b1 = bias[cc + 1];
        #pragma unroll
        for (int mi = 0; mi < 4; mi++) {
            const int r = row0 + mi * 16;
            float v00 = d[mi][ni][0] + b0, v01 = d[mi][ni][1] + b1;
            float v10 = d[mi][ni][2] + b0, v11 = d[mi][ni][3] + b1;
            if (tf32_out) {
                v00 = __uint_as_float(f2tf32(v00));
                v01 = __uint_as_float(f2tf32(v01));
                v10 = __uint_as_float(f2tf32(v10));
                v11 = __uint_as_float(f2tf32(v11));
            }
            float2 w0 = {v00, v01};
            float2 w1 = {v10, v11};
            *(float2*)(C + (size_t)r * GN + cc) = w0;
            *(float2*)(C + (size_t)(r + 8) * GN + cc) = w1;
        }
    }
}

// ---------------------------------------------------------------------------
// Flash attention (causal) on mma.sync tf32.
// Block = (b, h, 128-row q tile); 256 threads / 8 warps; 64-key iterations.
// Inputs Q/K/V already tf32-rounded by projection epilogue.
// smem (floats):
//   [0, 8960)      stage1 K/V (also Q staging during prologue: 128x68=8704)
//   [8960, 17920)  stage0 K/V
//   [17920, 26624) Ps 128x68
// ---------------------------------------------------------------------------
#define KS 68
#define VS 72
#define STAGE_F  8960                 // 64*68 + 64*72
#define OFF_ST1  0
#define OFF_QS   0
#define OFF_ST0  8960
#define OFF_PS   17920
#define ATT_SMEM_F 26624
#define ATT_DYN_SMEM (ATT_SMEM_F * 4) // 106496 B

__global__ __launch_bounds__(256)
void attn_mma(const float* __restrict__ Q, const float* __restrict__ K,
              const float* __restrict__ V, float* __restrict__ O)
{
    extern __shared__ float sm[];
    const int tid  = threadIdx.x;
    const int lane = tid & 31;
    const int warp = tid >> 5;          // 0..7
    const int r    = lane >> 2;         // 0..7
    const int cth  = lane & 3;          // 0..3
    const int qi   = gridDim.x - 1 - blockIdx.x;  // heavy tiles first
    const int hd   = blockIdx.y;
    const int b    = blockIdx.z;
    const int q0   = qi * 128;

    const float* Qg = Q + ((size_t)b * Ll + q0) * Dm + hd * 64;
    const float* Kg = K + (size_t)b * Ll * Dm + hd * 64;
    const float* Vg = V + (size_t)b * Ll * Dm + hd * 64;

    // Prologue: cp.async Q tile (group 0) and KV stage0 (group 1)
    #pragma unroll
    for (int i = 0; i < 8; i++) {
        const int id = tid + i * 256;        // 0..2047
        const int row = id >> 4, cg = id & 15;
        CP16(smem_u32(sm + OFF_QS + row * KS + cg * 4),
             Qg + (size_t)row * Dm + cg * 4);
    }
    asm volatile("cp.async.commit_group;");

    auto fillKV = [&](int kt, float* dst) {
        const int k0 = kt * 64;
        float* dK = dst;
        float* dV = dst + 64 * KS;
        #pragma unroll
        for (int i = 0; i < 4; i++) {
            const int id = tid + i * 256;    // 0..1023
            const int row = id >> 4, cg = id & 15;
            const float* gsrc = Kg + (size_t)(k0 + row) * Dm + cg * 4;
            CP16(smem_u32(dK + row * KS + cg * 4), gsrc);
            const float* gv = Vg + (size_t)(k0 + row) * Dm + cg * 4;
            CP16(smem_u32(dV + row * VS + cg * 4), gv);
        }
        asm volatile("cp.async.commit_group;");
    };

    fillKV(0, sm + OFF_ST0);

    // wait for Q (allow KV0 pending)
    asm volatile("cp.async.wait_group 1;" ::: "memory");
    __syncthreads();

    // Preload Q fragments (pre-scaled by 1/sqrt(64) = 0.125; values are
    // tf32-rounded and 0.125 is a power of two, so bits stay tf32-exact).
    uint32_t qf[8][4];
    {
        const float* qb = sm + OFF_QS + (warp * 16 + r) * KS + cth;
        #pragma unroll
        for (int j = 0; j < 8; j++) {
            qf[j][0] = __float_as_uint(0.125f * qb[j * 8]);
            qf[j][1] = __float_as_uint(0.125f * qb[8 * KS + j * 8]);
            qf[j][2] = __float_as_uint(0.125f * qb[j * 8 + 4]);
            qf[j][3] = __float_as_uint(0.125f * qb[8 * KS + j * 8 + 4]);
        }
    }
    __syncthreads();   // everyone done reading Q staging area

    const int ktmax = 2 * qi + 2;
    if (ktmax > 1) fillKV(1, sm + OFF_ST1);

    float m_i[2] = {-1e30f, -1e30f};
    float l_i[2] = {0.f, 0.f};
    float o[8][4];
    #pragma unroll
    for (int ni = 0; ni < 8; ni++)
        #pragma unroll
        for (int x = 0; x < 4; x++) o[ni][x] = 0.f;

    float* Ps = sm + OFF_PS;

    for (int kt = 0; kt < ktmax; kt++) {
        const int s = kt & 1;
        const float* Kt = sm + (s ? OFF_ST1 : OFF_ST0);
        const float* Vt = Kt + 64 * KS;

        asm volatile("cp.async.wait_group 1;" ::: "memory");
        __syncthreads();

        // S = (Q*scale) K^T
        float sacc[8][4];
        #pragma unroll
        for (int ni = 0; ni < 8; ni++)
            #pragma unroll
            for (int x = 0; x < 4; x++) sacc[ni][x] = 0.f;

        #pragma unroll
        for (int j = 0; j < 8; j++) {       // k-tiles over d
            uint32_t bf[8][2];
            #pragma unroll
            for (int ni = 0; ni < 8; ni++) {
                const float* p = Kt + (ni * 8 + r) * KS + j * 8 + cth;
                bf[ni][0] = __float_as_uint(p[0]);
                bf[ni][1] = __float_as_uint(p[4]);
            }
            #pragma unroll
            for (int ni = 0; ni < 8; ni++)
                mma_tf32(sacc[ni], qf[j], bf[ni]);
        }

        // causal mask (only last two iterations can touch the diagonal)
        const int k0 = kt * 64;
        if (k0 + 63 > q0) {
            const int rowb = q0 + warp * 16 + r;
            #pragma unroll
            for (int ni = 0; ni < 8; ni++) {
                const int colb = k0 + ni * 8 + 2 * cth;
                #pragma unroll
                for (int x = 0; x < 4; x++) {
                    const int row = rowb + 8 * (x >> 1);
                    const int col = colb + (x & 1);
                    if (col > row) sacc[ni][x] = -1e30f;
                }
            }
        }

        // online softmax (two row-halves per thread)
        #pragma unroll
        for (int h = 0; h < 2; h++) {
            float mx = -1e30f;
            #pragma unroll
            for (int ni = 0; ni < 8; ni++)
                mx = fmaxf(mx, fmaxf(sacc[ni][2 * h], sacc[ni][2 * h + 1]));
            mx = fmaxf(mx, __shfl_xor_sync(0xffffffffu, mx, 1));
            mx = fmaxf(mx, __shfl_xor_sync(0xffffffffu, mx, 2));
            const float mnew = fmaxf(m_i[h], mx);
            const float alpha = __expf(m_i[h] - mnew);
            float sum = 0.f;
            const int prow = warp * 16 + r + 8 * h;
            #pragma unroll
            for (int ni = 0; ni < 8; ni++) {
                const float p0 = __expf(sacc[ni][2 * h] - mnew);
                const float p1 = __expf(sacc[ni][2 * h + 1] - mnew);
                sum += p0 + p1;
                uint2 pv = {f2tf32(p0), f2tf32(p1)};
                *(uint2*)&Ps[prow * KS + ni * 8 + 2 * cth] = pv;
                o[ni][2 * h]     *= alpha;
                o[ni][2 * h + 1] *= alpha;
            }
            sum += __shfl_xor_sync(0xffffffffu, sum, 1);
            sum += __shfl_xor_sync(0xffffffffu, sum, 2);
            l_i[h] = l_i[h] * alpha + sum;
            m_i[h] = mnew;
        }
        __syncwarp();

        // O += P V
        #pragma unroll
        for (int kk = 0; kk < 8; kk++) {    // k-tiles over keys
            uint32_t af[4];
            const float* pb = Ps + (warp * 16 + r) * KS + kk * 8 + cth;
            af[0] = __float_as_uint(pb[0]);
            af[1] = __float_as_uint(pb[8 * KS]);
            af[2] = __float_as_uint(pb[4]);
            af[3] = __float_as_uint(pb[8 * KS + 4]);
            #pragma unroll
            for (int ni = 0; ni < 8; ni++) {
                const float* vb = Vt + (kk * 8 + cth) * VS + ni * 8 + r;
                uint32_t bf[2];
                bf[0] = __float_as_uint(vb[0]);
                bf[1] = __float_as_uint(vb[4 * VS]);
                mma_tf32(o[ni], af, bf);
            }
        }

        __syncthreads();   // all warps done reading stage s
        if (kt + 2 < ktmax) fillKV(kt + 2, sm + (s ? OFF_ST1 : OFF_ST0));
        else asm volatile("cp.async.commit_group;");  // keep group count
    }

    // normalize + write context [B,L,D]
    #pragma unroll
    for (int h = 0; h < 2; h++) {
        const float inv = 1.0f / l_i[h];
        const int row = q0 + warp * 16 + r + 8 * h;
        float* orow = O + ((size_t)b * Ll + row) * Dm + hd * 64;
        #pragma unroll
        for (int ni = 0; ni < 8; ni++) {
            float2 w = {o[ni][2 * h] * inv, o[ni][2 * h + 1] * inv};
            *(float2*)(orow + ni * 8 + 2 * cth) = w;
        }
    }
}

// ---------------------------------------------------------------------------
extern "C" void kernel_launch(void* const* d_in, const int* in_sizes, int n_in,
                              void* d_out, int out_size)
{
    const float* q    = (const float*)d_in[0];
    const float* k    = (const float*)d_in[1];
    const float* v    = (const float*)d_in[2];
    const float* wq_w = (const float*)d_in[3];
    const float* wq_b = (const float*)d_in[4];
    const float* wk_w = (const float*)d_in[5];
    const float* wk_b = (const float*)d_in[6];
    const float* wv_w = (const float*)d_in[7];
    const float* wv_b = (const float*)d_in[8];
    const float* wo_w = (const float*)d_in[9];
    const float* wo_b = (const float*)d_in[10];
    float* out = (float*)d_out;

    float *Qs, *Ks, *Vs, *Cs;
    cudaGetSymbolAddress((void**)&Qs, g_Q);
    cudaGetSymbolAddress((void**)&Ks, g_K);
    cudaGetSymbolAddress((void**)&Vs, g_V);
    cudaGetSymbolAddress((void**)&Cs, g_CTX);

    cudaFuncSetAttribute(gemm_mma_tf32, cudaFuncAttributeMaxDynamicSharedMemorySize,
                         GEMM_DYN_SMEM);
    cudaFuncSetAttribute(attn_mma, cudaFuncAttributeMaxDynamicSharedMemorySize,
                         ATT_DYN_SMEM);

    dim3 gg(GN / 128, MTOT / 128);   // (8, 64)
    dim3 gbk(128);

    gemm_mma_tf32<<<gg, gbk, GEMM_DYN_SMEM>>>(q, wq_w, wq_b, Qs, 1);
    gemm_mma_tf32<<<gg, gbk, GEMM_DYN_SMEM>>>(k, wk_w, wk_b, Ks, 1);
    gemm_mma_tf32<<<gg, gbk, GEMM_DYN_SMEM>>>(v, wv_w, wv_b, Vs, 1);

    dim3 ga(Ll / 128, Hh, Bb);       // (16, 16, 4)
    attn_mma<<<ga, 256, ATT_DYN_SMEM>>>(Qs, Ks, Vs, Cs);

    gemm_mma_tf32<<<gg, gbk, GEMM_DYN_SMEM>>>(Cs, wo_w, wo_b, out, 0);
}